// round 6
// baseline (speedup 1.0000x reference)
#include <cuda_runtime.h>

// MWPT: 3-level wavelet packet transform, fused, polyphase smem layout.
// Stores issued from compute registers; owned chunks handled by BRANCH-FREE
// fully-unrolled main loops, halo chunks by a tiny side loop (first warp).
//
// conv: out[n] = sum_k in[(2n + k - 3) mod L] * w[k]  (circular, stride 2)
// hi-pass QMF: wh[k] = (-1)^k * wl[7-k]
// out = concat(level1 [128,2,32768], level2 [128,4,16384], level3 [128,8,8192])
// level2 node order [b0,b2,b6,b4]; level3 [c0,c1,c3,c2,c6,c7,c5,c4].
//
// Index algebra (validated in R4):
//  x staged from jbase = 8n0-28 (even): xE[i]=x[jbase+2i], xO[i]=x[jbase+2i+1]
//  a_alpha (alpha = m-4n0+12), alpha in [0,2072):
//      a_alpha = sum_j xO[alpha+j]wl[2j] + xE[alpha+j+1]wl[2j+1]
//      owned alpha in [12,12+2048); aE[v]=a_{2v}, aO[v]=a_{2v+1}
//  b_beta (beta = l-2n0+4), beta in [0,1032):
//      b_beta = sum_j aO[beta+j]wl[2j] + aE[beta+j+1]wl[2j+1]
//      owned beta in [4,4+1024); bE[v]=b_{2v}, bO[v]=b_{2v+1}
//  c_r (r = i-n0) in [0,512): c_r = sum_j bO[r+j]wl[2j] + bE[r+j+1]wl[2j+1]

namespace {
constexpr int T   = 65536, MSK = T - 1, KS = 8;
constexpr int N3  = 512;
constexpr int THREADS = 256;
constexpr int XSZ = 2080;            // per parity (2076 used)
constexpr int ASZ = 1040;            // per array  (1036 used)
constexpr int BSZ = 520;             // per array  (516 used)
constexpr int XREG = 2 * XSZ;        // 4160 floats; aliased by 8*BSZ = 4160
constexpr int SMEM_FLOATS = XREG + 4 * ASZ;   // 8320
constexpr int SMEM_BYTES  = SMEM_FLOATS * 4;  // 33280
constexpr long OUT2_BASE = 128L * 2 * 32768;
constexpr long OUT3_BASE = OUT2_BASE + 128L * 4 * 16384;
}

__device__ __forceinline__ void ld8(const float* s, float v[8]) {
    float4 a = *(const float4*)s;        // bases always 16B-aligned
    float4 b = *(const float4*)(s + 4);
    v[0]=a.x; v[1]=a.y; v[2]=a.z; v[3]=a.w;
    v[4]=b.x; v[5]=b.y; v[6]=b.z; v[7]=b.w;
}

// lo[p] = sum_j O[p+j]*wl[2j] + E[p+j+1]*wl[2j+1]; hi likewise with wh.
__device__ __forceinline__ void qmf4(const float O[8], const float E[8],
                                     const float wl[KS], const float wh[KS],
                                     float lo[4], float hi[4]) {
    #pragma unroll
    for (int p = 0; p < 4; ++p) {
        float l = 0.f, h = 0.f;
        #pragma unroll
        for (int j = 0; j < 4; ++j) {
            float o = O[p + j], e = E[p + j + 1];
            l += o * wl[2*j] + e * wl[2*j+1];
            h += o * wh[2*j] + e * wh[2*j+1];
        }
        lo[p] = l; hi[p] = h;
    }
}

__global__ __launch_bounds__(THREADS, 6) void mwpt_kernel(
    const float* __restrict__ x,
    const float* __restrict__ kern,
    float* __restrict__ out)
{
    extern __shared__ float sm[];
    float* xE  = sm;                 // [XSZ]
    float* xO  = sm + XSZ;           // [XSZ]
    float* aE0 = sm + XREG;          // [ASZ] x4
    float* aO0 = aE0 + ASZ;
    float* aE4 = aO0 + ASZ;
    float* aO4 = aE4 + ASZ;
    // b arrays alias x region (x dead after level-1):
    // parent n in {b0,b2,b4,b6}: bE = sm + n*2*BSZ, bO = bE + BSZ

    const int b   = blockIdx.y;
    const int n0  = blockIdx.x * N3;
    const int tid = threadIdx.x;

    float wl[KS], wh[KS];
    #pragma unroll
    for (int k = 0; k < KS; ++k) wl[k] = __ldg(&kern[k]);
    #pragma unroll
    for (int k = 0; k < KS; ++k) wh[k] = (k & 1) ? -wl[KS-1-k] : wl[KS-1-k];

    // ---- Stage x, parity-split. jbase ≡ 0 mod 4 -> aligned LDG.128. ----
    {
        const int jbase = 8 * n0 - 28;
        const float* xb = x + (size_t)b * T;
        #pragma unroll
        for (int it = 0; it < 5; ++it) {           // 5*256 = 1280 >= 1040
            const int i4 = it * THREADS + tid;     // float4 index (2 E + 2 O)
            if (i4 < 1040) {
                float4 v = *(const float4*)(xb + ((jbase + 4 * i4) & MSK));
                *(float2*)(xE + 2 * i4) = make_float2(v.x, v.z);
                *(float2*)(xO + 2 * i4) = make_float2(v.y, v.w);
            }
        }
    }
    __syncthreads();

    // ================= Level 1 =================
    {
        float* o1 = out + (size_t)b * (2 * 32768) + 4 * n0;
        // halo chunks {0,1,2,515,516,517}: compute only (one warp)
        if (tid < 6) {
            const int g = (tid < 3) ? tid : 512 + tid;
            float o8[8], e8[8], lo[4], hi[4];
            ld8(xO + 4*g, o8);
            ld8(xE + 4*g, e8);
            qmf4(o8, e8, wl, wh, lo, hi);
            *(float2*)(aE0 + 2*g) = make_float2(lo[0], lo[2]);
            *(float2*)(aO0 + 2*g) = make_float2(lo[1], lo[3]);
            *(float2*)(aE4 + 2*g) = make_float2(hi[0], hi[2]);
            *(float2*)(aO4 + 2*g) = make_float2(hi[1], hi[3]);
        }
        // owned chunks: g = g'+3, g' in [0,512); branch-free, 2 unrolled trips
        #pragma unroll
        for (int it = 0; it < 2; ++it) {
            const int gp = it * THREADS + tid;
            const int g  = gp + 3;
            float o8[8], e8[8], lo[4], hi[4];
            ld8(xO + 4*g, o8);
            ld8(xE + 4*g, e8);
            qmf4(o8, e8, wl, wh, lo, hi);
            *(float2*)(aE0 + 2*g) = make_float2(lo[0], lo[2]);
            *(float2*)(aO0 + 2*g) = make_float2(lo[1], lo[3]);
            *(float2*)(aE4 + 2*g) = make_float2(hi[0], hi[2]);
            *(float2*)(aO4 + 2*g) = make_float2(hi[1], hi[3]);
            *(float4*)(o1 + 4*gp)         = make_float4(lo[0], lo[1], lo[2], lo[3]);
            *(float4*)(o1 + 32768 + 4*gp) = make_float4(hi[0], hi[1], hi[2], hi[3]);
        }
    }
    __syncthreads();

    // ================= Level 2 =================
    {
        float* o2 = out + OUT2_BASE + (size_t)b * (4 * 16384) + 2 * n0;
        // halo: h in {0, 257} per parent: 4 items (one warp)
        if (tid < 4) {
            const int par = tid >> 1;
            const int h   = (tid & 1) ? 257 : 0;
            const float* AE = par ? aE4 : aE0;
            const float* AO = par ? aO4 : aO0;
            float* bLoE = sm + (2*par)     * (2*BSZ);
            float* bHiE = sm + (2*par + 1) * (2*BSZ);
            float o8[8], e8[8], lo[4], hi[4];
            ld8(AO + 4*h, o8);
            ld8(AE + 4*h, e8);
            qmf4(o8, e8, wl, wh, lo, hi);
            *(float2*)(bLoE + 2*h)       = make_float2(lo[0], lo[2]);
            *(float2*)(bLoE + BSZ + 2*h) = make_float2(lo[1], lo[3]);
            *(float2*)(bHiE + 2*h)       = make_float2(hi[0], hi[2]);
            *(float2*)(bHiE + BSZ + 2*h) = make_float2(hi[1], hi[3]);
        }
        // owned: h = h'+1, h' = tid in [0,256); one trip per parent, unrolled
        #pragma unroll
        for (int par = 0; par < 2; ++par) {
            const float* AE = par ? aE4 : aE0;
            const float* AO = par ? aO4 : aO0;
            float* bLoE = sm + (2*par)     * (2*BSZ);
            float* bHiE = sm + (2*par + 1) * (2*BSZ);
            const int pos_lo = par ? 3 : 0;   // b0->0, b4->3
            const int pos_hi = par ? 2 : 1;   // b2->1, b6->2
            const int h = tid + 1;
            float o8[8], e8[8], lo[4], hi[4];
            ld8(AO + 4*h, o8);
            ld8(AE + 4*h, e8);
            qmf4(o8, e8, wl, wh, lo, hi);
            *(float2*)(bLoE + 2*h)       = make_float2(lo[0], lo[2]);
            *(float2*)(bLoE + BSZ + 2*h) = make_float2(lo[1], lo[3]);
            *(float2*)(bHiE + 2*h)       = make_float2(hi[0], hi[2]);
            *(float2*)(bHiE + BSZ + 2*h) = make_float2(hi[1], hi[3]);
            *(float4*)(o2 + pos_lo * 16384 + 4*tid) =
                make_float4(lo[0], lo[1], lo[2], lo[3]);
            *(float4*)(o2 + pos_hi * 16384 + 4*tid) =
                make_float4(hi[0], hi[1], hi[2], hi[3]);
        }
    }
    __syncthreads();

    // ================= Level 3 =================
    // parent n (b0,b2,b4,b6) -> children pos_lo={0,3,7,4}, pos_hi={1,2,6,5}
    {
        float* o3 = out + OUT3_BASE + (size_t)b * (8 * 8192) + n0;
        #pragma unroll
        for (int it = 0; it < 2; ++it) {
            const int t   = it * THREADS + tid;
            const int par = t >> 7;               // warp-uniform
            const int g   = t & 127;
            const float* bE = sm + par * (2*BSZ);
            const float* bO = bE + BSZ;
            float o8[8], e8[8], lo[4], hi[4];
            ld8(bO + 4*g, o8);
            ld8(bE + 4*g, e8);
            qmf4(o8, e8, wl, wh, lo, hi);
            const int pos_lo = (par == 0) ? 0 : (par == 1) ? 3 : (par == 2) ? 7 : 4;
            const int pos_hi = (par == 0) ? 1 : (par == 1) ? 2 : (par == 2) ? 6 : 5;
            *(float4*)(o3 + pos_lo * 8192 + 4*g) = make_float4(lo[0], lo[1], lo[2], lo[3]);
            *(float4*)(o3 + pos_hi * 8192 + 4*g) = make_float4(hi[0], hi[1], hi[2], hi[3]);
        }
    }
}

extern "C" void kernel_launch(void* const* d_in, const int* in_sizes, int n_in,
                              void* d_out, int out_size)
{
    const float* x    = (const float*)d_in[0];
    const float* kern = (const float*)d_in[1];
    float* out        = (float*)d_out;

    cudaFuncSetAttribute(mwpt_kernel,
                         cudaFuncAttributeMaxDynamicSharedMemorySize,
                         SMEM_BYTES);

    dim3 grid(8192 / N3, 128);   // 16 x 128 = 2048 blocks
    mwpt_kernel<<<grid, THREADS, SMEM_BYTES>>>(x, kern, out);
}

// round 7
// speedup vs baseline: 1.0088x; 1.0088x over previous
#include <cuda_runtime.h>

// MWPT: 3-level wavelet packet transform, fused, polyphase smem layout.
// Levels 2-3 use fma.rn.f32x2 with parent-paired lanes: intermediates stored
// interleaved by parent node as float2, so every LDS yields a ready 2-lane
// operand (zero pack overhead). Level 1 scalar.
//
// conv: out[n] = sum_k in[(2n + k - 3) mod L] * w[k]  (circular, stride 2)
// hi-pass QMF: wh[k] = (-1)^k * wl[7-k]
// out = concat(level1 [128,2,32768], level2 [128,4,16384], level3 [128,8,8192])
// level2 node order [b0,b2,b6,b4]; level3 [c0,c1,c3,c2,c6,c7,c5,c4].
//
// Index algebra (validated R3-R5):
//  x staged from jbase=8n0-28: xE[i]=x[jbase+2i], xO[i]=x[jbase+2i+1]
//  a_alpha (alpha=m-4n0+12): a = sum_j xO[a+j]wl[2j] + xE[a+j+1]wl[2j+1]
//     owned alpha in [12,2060); pairs pAE[v]=(a0,a4)_{2v}, pAO[v]=(a0,a4)_{2v+1}
//  b_beta (beta=l-2n0+4): b = sum_j aO[b+j]wl[2j] + aE[b+j+1]wl[2j+1]
//     owned beta in [4,1028); fam0=(b0,b4), fam1=(b2,b6): BE_f[v]=b_{2v}, BO_f[v]=b_{2v+1}
//  c_r (r=i-n0) in [0,512): c = sum_j bO[r+j]wl[2j] + bE[r+j+1]wl[2j+1]

namespace {
constexpr int T   = 65536, MSK = T - 1, KS = 8;
constexpr int N3  = 512;
constexpr int THREADS = 256;
constexpr int XSZ  = 2080;              // floats per x parity
constexpr int XREG = 2 * XSZ;           // 4160 floats; aliased by 4*BSZ2 float2
constexpr int ASZ2 = 1040;              // float2 per pA array (x2)
constexpr int BSZ2 = 520;               // float2 per b array (x4) = 4160 floats
constexpr int SMEM_FLOATS = XREG + 4 * ASZ2;  // 8320
constexpr int SMEM_BYTES  = SMEM_FLOATS * 4;  // 33280
constexpr long OUT2_BASE = 128L * 2 * 32768;
constexpr long OUT3_BASE = OUT2_BASE + 128L * 4 * 16384;
}

using u64 = unsigned long long;
union F2U { u64 u; float2 f; };

__device__ __forceinline__ u64 bcast2(float a) {
    u64 r; asm("mov.b64 %0, {%1, %1};" : "=l"(r) : "f"(a)); return r;
}
__device__ __forceinline__ u64 mul2(u64 a, u64 b) {
    u64 d; asm("mul.rn.f32x2 %0, %1, %2;" : "=l"(d) : "l"(a), "l"(b)); return d;
}
__device__ __forceinline__ void fma2(u64& d, u64 a, u64 b) {
    asm("fma.rn.f32x2 %0, %1, %2, %0;" : "+l"(d) : "l"(a), "l"(b));
}

__device__ __forceinline__ void ld8(const float* s, float v[8]) {
    float4 a = *(const float4*)s;
    float4 b = *(const float4*)(s + 4);
    v[0]=a.x; v[1]=a.y; v[2]=a.z; v[3]=a.w;
    v[4]=b.x; v[5]=b.y; v[6]=b.z; v[7]=b.w;
}
__device__ __forceinline__ void ld8p(const float2* s, u64 v[8]) {
    const ulonglong2* p = (const ulonglong2*)s;   // 16B-aligned by construction
    #pragma unroll
    for (int i = 0; i < 4; ++i) { ulonglong2 q = p[i]; v[2*i] = q.x; v[2*i+1] = q.y; }
}

// scalar: lo[p] = sum_j O[p+j]wl[2j] + E[p+j+1]wl[2j+1]; hi with wh
__device__ __forceinline__ void qmf4(const float O[8], const float E[8],
                                     const float wl[KS], const float wh[KS],
                                     float lo[4], float hi[4]) {
    #pragma unroll
    for (int p = 0; p < 4; ++p) {
        float l = 0.f, h = 0.f;
        #pragma unroll
        for (int j = 0; j < 4; ++j) {
            float o = O[p + j], e = E[p + j + 1];
            l += o * wl[2*j] + e * wl[2*j+1];
            h += o * wh[2*j] + e * wh[2*j+1];
        }
        lo[p] = l; hi[p] = h;
    }
}

// packed 2-lane version (both lanes share coefficients)
__device__ __forceinline__ void qmf4p(const u64 O[8], const u64 E[8],
                                      const u64 bl[KS], const u64 bh[KS],
                                      u64 aL[4], u64 aH[4]) {
    #pragma unroll
    for (int p = 0; p < 4; ++p) {
        u64 l = mul2(O[p], bl[0]);
        u64 h = mul2(O[p], bh[0]);
        fma2(l, E[p+1], bl[1]);
        fma2(h, E[p+1], bh[1]);
        #pragma unroll
        for (int j = 1; j < 4; ++j) {
            fma2(l, O[p+j],   bl[2*j]);   fma2(l, E[p+j+1], bl[2*j+1]);
            fma2(h, O[p+j],   bh[2*j]);   fma2(h, E[p+j+1], bh[2*j+1]);
        }
        aL[p] = l; aH[p] = h;
    }
}

__global__ __launch_bounds__(THREADS, 3) void mwpt_kernel(
    const float* __restrict__ x,
    const float* __restrict__ kern,
    float* __restrict__ out)
{
    extern __shared__ float sm[];
    float*  xE  = sm;                        // [XSZ]
    float*  xO  = sm + XSZ;                  // [XSZ]
    float2* pAE = (float2*)(sm + XREG);      // [ASZ2] (a0,a4) even polyphase
    float2* pAO = pAE + ASZ2;                // [ASZ2] odd
    // b pair arrays alias x region: BEf0, BOf0, BEf1, BOf1 (each BSZ2 float2)

    const int b   = blockIdx.y;
    const int n0  = blockIdx.x * N3;
    const int tid = threadIdx.x;

    float wl[KS], wh[KS];
    #pragma unroll
    for (int k = 0; k < KS; ++k) wl[k] = __ldg(&kern[k]);
    #pragma unroll
    for (int k = 0; k < KS; ++k) wh[k] = (k & 1) ? -wl[KS-1-k] : wl[KS-1-k];
    u64 bl[KS], bh[KS];
    #pragma unroll
    for (int k = 0; k < KS; ++k) { bl[k] = bcast2(wl[k]); bh[k] = bcast2(wh[k]); }

    // ---- Stage x, parity-split (aligned LDG.128) ----
    {
        const int jbase = 8 * n0 - 28;
        const float* xb = x + (size_t)b * T;
        #pragma unroll
        for (int it = 0; it < 5; ++it) {
            const int i4 = it * THREADS + tid;
            if (i4 < 1040) {
                float4 v = *(const float4*)(xb + ((jbase + 4 * i4) & MSK));
                *(float2*)(xE + 2 * i4) = make_float2(v.x, v.z);
                *(float2*)(xO + 2 * i4) = make_float2(v.y, v.w);
            }
        }
    }
    __syncthreads();

    // ================= Level 1 (scalar) =================
    {
        float* o1 = out + (size_t)b * (2 * 32768) + 4 * n0;
        if (tid < 6) {                       // halo chunks {0,1,2,515,516,517}
            const int g = (tid < 3) ? tid : 512 + tid;
            float o8[8], e8[8], lo[4], hi[4];
            ld8(xO + 4*g, o8);
            ld8(xE + 4*g, e8);
            qmf4(o8, e8, wl, wh, lo, hi);
            *(float4*)(pAE + 2*g) = make_float4(lo[0], hi[0], lo[2], hi[2]);
            *(float4*)(pAO + 2*g) = make_float4(lo[1], hi[1], lo[3], hi[3]);
        }
        #pragma unroll
        for (int it = 0; it < 2; ++it) {     // owned: g = gp+3, branch-free
            const int gp = it * THREADS + tid;
            const int g  = gp + 3;
            float o8[8], e8[8], lo[4], hi[4];
            ld8(xO + 4*g, o8);
            ld8(xE + 4*g, e8);
            qmf4(o8, e8, wl, wh, lo, hi);
            *(float4*)(pAE + 2*g) = make_float4(lo[0], hi[0], lo[2], hi[2]);
            *(float4*)(pAO + 2*g) = make_float4(lo[1], hi[1], lo[3], hi[3]);
            *(float4*)(o1 + 4*gp)         = make_float4(lo[0], lo[1], lo[2], lo[3]);
            *(float4*)(o1 + 32768 + 4*gp) = make_float4(hi[0], hi[1], hi[2], hi[3]);
        }
    }
    __syncthreads();

    // ================= Level 2 (f32x2, lanes = (a0,a4)) =================
    // accL lanes -> (b0,b4) = fam0; accH lanes -> (b2,b6) = fam1
    {
        float2* BEf0 = (float2*)sm;
        float2* BOf0 = BEf0 + BSZ2;
        float2* BEf1 = BOf0 + BSZ2;
        float2* BOf1 = BEf1 + BSZ2;
        if (tid < 2) {                       // halo chunks h in {0, 257}
            const int h = tid ? 257 : 0;
            u64 o8[8], e8[8], aL[4], aH[4];
            ld8p(pAO + 4*h, o8);
            ld8p(pAE + 4*h, e8);
            qmf4p(o8, e8, bl, bh, aL, aH);
            *(ulonglong2*)(BEf0 + 2*h) = make_ulonglong2(aL[0], aL[2]);
            *(ulonglong2*)(BOf0 + 2*h) = make_ulonglong2(aL[1], aL[3]);
            *(ulonglong2*)(BEf1 + 2*h) = make_ulonglong2(aH[0], aH[2]);
            *(ulonglong2*)(BOf1 + 2*h) = make_ulonglong2(aH[1], aH[3]);
        }
        {                                    // owned: h = tid+1, branch-free
            const int h = tid + 1;
            u64 o8[8], e8[8], aL[4], aH[4];
            ld8p(pAO + 4*h, o8);
            ld8p(pAE + 4*h, e8);
            qmf4p(o8, e8, bl, bh, aL, aH);
            *(ulonglong2*)(BEf0 + 2*h) = make_ulonglong2(aL[0], aL[2]);
            *(ulonglong2*)(BOf0 + 2*h) = make_ulonglong2(aL[1], aL[3]);
            *(ulonglong2*)(BEf1 + 2*h) = make_ulonglong2(aH[0], aH[2]);
            *(ulonglong2*)(BOf1 + 2*h) = make_ulonglong2(aH[1], aH[3]);
            // gmem: b0->pos0 (L.x), b2->pos1 (H.x), b6->pos2 (H.y), b4->pos3 (L.y)
            float* o2 = out + OUT2_BASE + (size_t)b * (4 * 16384) + 2 * n0 + 4 * tid;
            F2U l0{aL[0]}, l1{aL[1]}, l2{aL[2]}, l3{aL[3]};
            F2U h0{aH[0]}, h1{aH[1]}, h2{aH[2]}, h3{aH[3]};
            *(float4*)(o2 + 0 * 16384) = make_float4(l0.f.x, l1.f.x, l2.f.x, l3.f.x);
            *(float4*)(o2 + 1 * 16384) = make_float4(h0.f.x, h1.f.x, h2.f.x, h3.f.x);
            *(float4*)(o2 + 2 * 16384) = make_float4(h0.f.y, h1.f.y, h2.f.y, h3.f.y);
            *(float4*)(o2 + 3 * 16384) = make_float4(l0.f.y, l1.f.y, l2.f.y, l3.f.y);
        }
    }
    __syncthreads();

    // ================= Level 3 (f32x2) =================
    // fam0 (b0,b4): cL=(c0,c4)->pos(0,7), cH=(c1,c5)->pos(1,6)
    // fam1 (b2,b6): cL=(c2,c6)->pos(3,4), cH=(c3,c7)->pos(2,5)
    {
        const int fam = tid >> 7;            // warp-uniform
        const int q   = tid & 127;
        const float2* BE = (float2*)sm + (size_t)fam * (2 * BSZ2);
        const float2* BO = BE + BSZ2;
        u64 o8[8], e8[8], cL[4], cH[4];
        ld8p(BO + 4*q, o8);
        ld8p(BE + 4*q, e8);
        qmf4p(o8, e8, bl, bh, cL, cH);
        float* o3 = out + OUT3_BASE + (size_t)b * (8 * 8192) + n0 + 4 * q;
        const int posLx = fam ? 3 : 0, posLy = fam ? 4 : 7;
        const int posHx = fam ? 2 : 1, posHy = fam ? 5 : 6;
        F2U l0{cL[0]}, l1{cL[1]}, l2{cL[2]}, l3{cL[3]};
        F2U h0{cH[0]}, h1{cH[1]}, h2{cH[2]}, h3{cH[3]};
        *(float4*)(o3 + posLx * 8192) = make_float4(l0.f.x, l1.f.x, l2.f.x, l3.f.x);
        *(float4*)(o3 + posLy * 8192) = make_float4(l0.f.y, l1.f.y, l2.f.y, l3.f.y);
        *(float4*)(o3 + posHx * 8192) = make_float4(h0.f.x, h1.f.x, h2.f.x, h3.f.x);
        *(float4*)(o3 + posHy * 8192) = make_float4(h0.f.y, h1.f.y, h2.f.y, h3.f.y);
    }
}

extern "C" void kernel_launch(void* const* d_in, const int* in_sizes, int n_in,
                              void* d_out, int out_size)
{
    const float* x    = (const float*)d_in[0];
    const float* kern = (const float*)d_in[1];
    float* out        = (float*)d_out;

    cudaFuncSetAttribute(mwpt_kernel,
                         cudaFuncAttributeMaxDynamicSharedMemorySize,
                         SMEM_BYTES);

    dim3 grid(8192 / N3, 128);   // 16 x 128 = 2048 blocks
    mwpt_kernel<<<grid, THREADS, SMEM_BYTES>>>(x, kern, out);
}

// round 8
// speedup vs baseline: 1.0760x; 1.0667x over previous
#include <cuda_runtime.h>

// MWPT: 3-level wavelet packet transform, fused, polyphase smem layout.
// Levels 2-3: fma.rn.f32x2 with parent-paired lanes. Pair arrays are
// SUB-PARITY SPLIT so every LDS is 16B/thread stride (conflict-free),
// fixing R7's 2x wavefront inflation while keeping the halved FMA count.
//
// conv: out[n] = sum_k in[(2n + k - 3) mod L] * w[k]  (circular, stride 2)
// hi-pass QMF: wh[k] = (-1)^k * wl[7-k]
// out = concat(level1 [128,2,32768], level2 [128,4,16384], level3 [128,8,8192])
// level2 node order [b0,b2,b6,b4]; level3 [c0,c1,c3,c2,c6,c7,c5,c4].
//
// Index algebra (validated R3-R7). Pair P[alpha]=(a0,a4)_alpha.
//  aE[v]=P[2v], aO[v]=P[2v+1]; sub-parity: aEe[u]=aE[2u], aEo[u]=aE[2u+1], etc.
//  Level-2 chunk h (beta=4h..4h+3): O[i]=aO[4h+i] -> even i: aOe[2h+i/2],
//  odd i: aOo[2h+(i-1)/2]; same for E from aEe/aEo. 4 runs of 4 float2.
//  b families: fam0=(b0,b4), fam1=(b2,b6), each split bEe,bOe,bEo,bOo.

namespace {
constexpr int T   = 65536, MSK = T - 1, KS = 8;
constexpr int N3  = 512;
constexpr int THREADS = 256;
constexpr int XSZ  = 2080;              // floats per x parity
constexpr int XREG = 2 * XSZ;           // 4160 floats; aliased by b sub-arrays
constexpr int ASUB = 520;               // float2 per a sub-array (518 used), x4
constexpr int BSUB = 260;               // float2 per b sub-array (258 used), x8
constexpr int SMEM_FLOATS = XREG + 4 * ASUB * 2;   // 8320
constexpr int SMEM_BYTES  = SMEM_FLOATS * 4;       // 33280
constexpr long OUT2_BASE = 128L * 2 * 32768;
constexpr long OUT3_BASE = OUT2_BASE + 128L * 4 * 16384;
}

using u64 = unsigned long long;
union F2U { u64 u; float2 f; };

__device__ __forceinline__ u64 bcast2(float a) {
    u64 r; asm("mov.b64 %0, {%1, %1};" : "=l"(r) : "f"(a)); return r;
}
__device__ __forceinline__ u64 mul2(u64 a, u64 b) {
    u64 d; asm("mul.rn.f32x2 %0, %1, %2;" : "=l"(d) : "l"(a), "l"(b)); return d;
}
__device__ __forceinline__ void fma2(u64& d, u64 a, u64 b) {
    asm("fma.rn.f32x2 %0, %1, %2, %0;" : "+l"(d) : "l"(a), "l"(b));
}

__device__ __forceinline__ void ld8(const float* s, float v[8]) {
    float4 a = *(const float4*)s;
    float4 b = *(const float4*)(s + 4);
    v[0]=a.x; v[1]=a.y; v[2]=a.z; v[3]=a.w;
    v[4]=b.x; v[5]=b.y; v[6]=b.z; v[7]=b.w;
}
// 4 consecutive float2 from sub-array: 2x LDS.128 at 16B/thread stride.
__device__ __forceinline__ void ld4p(const float2* s, int i, u64 v[4]) {
    const ulonglong2* p = (const ulonglong2*)(s + i);
    ulonglong2 q0 = p[0], q1 = p[1];
    v[0]=q0.x; v[1]=q0.y; v[2]=q1.x; v[3]=q1.y;
}

// scalar: lo[p] = sum_j O[p+j]wl[2j] + E[p+j+1]wl[2j+1]; hi with wh
__device__ __forceinline__ void qmf4(const float O[8], const float E[8],
                                     const float wl[KS], const float wh[KS],
                                     float lo[4], float hi[4]) {
    #pragma unroll
    for (int p = 0; p < 4; ++p) {
        float l = 0.f, h = 0.f;
        #pragma unroll
        for (int j = 0; j < 4; ++j) {
            float o = O[p + j], e = E[p + j + 1];
            l += o * wl[2*j] + e * wl[2*j+1];
            h += o * wh[2*j] + e * wh[2*j+1];
        }
        lo[p] = l; hi[p] = h;
    }
}

// packed 2-lane version (lanes share coefficients)
__device__ __forceinline__ void qmf4p(const u64 O[8], const u64 E[8],
                                      const u64 bl[KS], const u64 bh[KS],
                                      u64 aL[4], u64 aH[4]) {
    #pragma unroll
    for (int p = 0; p < 4; ++p) {
        u64 l = mul2(O[p], bl[0]);
        u64 h = mul2(O[p], bh[0]);
        fma2(l, E[p+1], bl[1]);
        fma2(h, E[p+1], bh[1]);
        #pragma unroll
        for (int j = 1; j < 4; ++j) {
            fma2(l, O[p+j],   bl[2*j]);   fma2(l, E[p+j+1], bl[2*j+1]);
            fma2(h, O[p+j],   bh[2*j]);   fma2(h, E[p+j+1], bh[2*j+1]);
        }
        aL[p] = l; aH[p] = h;
    }
}

__global__ __launch_bounds__(THREADS, 4) void mwpt_kernel(
    const float* __restrict__ x,
    const float* __restrict__ kern,
    float* __restrict__ out)
{
    extern __shared__ float sm[];
    float*  xE  = sm;                          // [XSZ]
    float*  xO  = sm + XSZ;                    // [XSZ]
    float2* aEe = (float2*)(sm + XREG);        // [ASUB] each
    float2* aOe = aEe + ASUB;
    float2* aEo = aOe + ASUB;
    float2* aOo = aEo + ASUB;
    // b sub-arrays alias x region: fam f at (float2*)sm + f*4*BSUB:
    //   bEe, bOe, bEo, bOo (each BSUB float2)

    const int b   = blockIdx.y;
    const int n0  = blockIdx.x * N3;
    const int tid = threadIdx.x;

    float wl[KS], wh[KS];
    #pragma unroll
    for (int k = 0; k < KS; ++k) wl[k] = __ldg(&kern[k]);
    #pragma unroll
    for (int k = 0; k < KS; ++k) wh[k] = (k & 1) ? -wl[KS-1-k] : wl[KS-1-k];
    u64 bl[KS], bh[KS];
    #pragma unroll
    for (int k = 0; k < KS; ++k) { bl[k] = bcast2(wl[k]); bh[k] = bcast2(wh[k]); }

    // ---- Stage x, parity-split (aligned LDG.128) ----
    {
        const int jbase = 8 * n0 - 28;
        const float* xb = x + (size_t)b * T;
        #pragma unroll
        for (int it = 0; it < 5; ++it) {
            const int i4 = it * THREADS + tid;
            if (i4 < 1040) {
                float4 v = *(const float4*)(xb + ((jbase + 4 * i4) & MSK));
                *(float2*)(xE + 2 * i4) = make_float2(v.x, v.z);
                *(float2*)(xO + 2 * i4) = make_float2(v.y, v.w);
            }
        }
    }
    __syncthreads();

    // ================= Level 1 (scalar) =================
    // chunk g -> alpha = 4g+p: p0->aEe[g], p1->aOe[g], p2->aEo[g], p3->aOo[g]
    {
        float* o1 = out + (size_t)b * (2 * 32768) + 4 * n0;
        if (tid < 6) {                         // halo chunks {0,1,2,515,516,517}
            const int g = (tid < 3) ? tid : 512 + tid;
            float o8[8], e8[8], lo[4], hi[4];
            ld8(xO + 4*g, o8);
            ld8(xE + 4*g, e8);
            qmf4(o8, e8, wl, wh, lo, hi);
            aEe[g] = make_float2(lo[0], hi[0]);
            aOe[g] = make_float2(lo[1], hi[1]);
            aEo[g] = make_float2(lo[2], hi[2]);
            aOo[g] = make_float2(lo[3], hi[3]);
        }
        #pragma unroll
        for (int it = 0; it < 2; ++it) {       // owned: g = gp+3, branch-free
            const int gp = it * THREADS + tid;
            const int g  = gp + 3;
            float o8[8], e8[8], lo[4], hi[4];
            ld8(xO + 4*g, o8);
            ld8(xE + 4*g, e8);
            qmf4(o8, e8, wl, wh, lo, hi);
            aEe[g] = make_float2(lo[0], hi[0]);
            aOe[g] = make_float2(lo[1], hi[1]);
            aEo[g] = make_float2(lo[2], hi[2]);
            aOo[g] = make_float2(lo[3], hi[3]);
            *(float4*)(o1 + 4*gp)         = make_float4(lo[0], lo[1], lo[2], lo[3]);
            *(float4*)(o1 + 32768 + 4*gp) = make_float4(hi[0], hi[1], hi[2], hi[3]);
        }
    }
    __syncthreads();

    // ================= Level 2 (f32x2, lanes = (a0,a4)) =================
    // chunk h: O[i]=aO[4h+i], E[i]=aE[4h+i]; accL->(b0,b4)=fam0, accH->(b2,b6)=fam1
    {
        float2* f0 = (float2*)sm;              // fam0: bEe,bOe,bEo,bOo
        float2* f1 = f0 + 4 * BSUB;            // fam1
        #pragma unroll
        for (int pass = 0; pass < 2; ++pass) {
            int h; bool owned;
            if (pass == 0) { h = tid + 1; owned = true; }       // h in [1,256]
            else {
                if (tid >= 2) break;
                h = tid ? 257 : 0; owned = false;               // halo
            }
            u64 OE[4], OO[4], EE[4], EO[4];
            ld4p(aOe, 2*h, OE);
            ld4p(aOo, 2*h, OO);
            ld4p(aEe, 2*h, EE);
            ld4p(aEo, 2*h, EO);
            u64 O[8] = {OE[0],OO[0],OE[1],OO[1],OE[2],OO[2],OE[3],OO[3]};
            u64 E[8] = {EE[0],EO[0],EE[1],EO[1],EE[2],EO[2],EE[3],EO[3]};
            u64 aL[4], aH[4];
            qmf4p(O, E, bl, bh, aL, aH);
            // beta=4h+p: p0->bEe[h], p1->bOe[h], p2->bEo[h], p3->bOo[h]
            *(u64*)(f0 + 0*BSUB + h) = aL[0];
            *(u64*)(f0 + 1*BSUB + h) = aL[1];
            *(u64*)(f0 + 2*BSUB + h) = aL[2];
            *(u64*)(f0 + 3*BSUB + h) = aL[3];
            *(u64*)(f1 + 0*BSUB + h) = aH[0];
            *(u64*)(f1 + 1*BSUB + h) = aH[1];
            *(u64*)(f1 + 2*BSUB + h) = aH[2];
            *(u64*)(f1 + 3*BSUB + h) = aH[3];
            if (owned) {
                // b0->pos0 (L.x), b2->pos1 (H.x), b6->pos2 (H.y), b4->pos3 (L.y)
                float* o2 = out + OUT2_BASE + (size_t)b * (4*16384) + 2*n0 + 4*tid;
                F2U l0{aL[0]}, l1{aL[1]}, l2{aL[2]}, l3{aL[3]};
                F2U h0{aH[0]}, h1{aH[1]}, h2{aH[2]}, h3{aH[3]};
                *(float4*)(o2 + 0*16384) = make_float4(l0.f.x, l1.f.x, l2.f.x, l3.f.x);
                *(float4*)(o2 + 1*16384) = make_float4(h0.f.x, h1.f.x, h2.f.x, h3.f.x);
                *(float4*)(o2 + 2*16384) = make_float4(h0.f.y, h1.f.y, h2.f.y, h3.f.y);
                *(float4*)(o2 + 3*16384) = make_float4(l0.f.y, l1.f.y, l2.f.y, l3.f.y);
            }
        }
    }
    __syncthreads();

    // ================= Level 3 (f32x2) =================
    // fam0 (b0,b4): cL=(c0,c4)->pos(0,7), cH=(c1,c5)->pos(1,6)
    // fam1 (b2,b6): cL=(c2,c6)->pos(3,4), cH=(c3,c7)->pos(2,5)
    {
        const int fam = tid >> 7;              // warp-uniform
        const int q   = tid & 127;
        const float2* fb = (float2*)sm + (size_t)fam * (4 * BSUB);
        u64 OE[4], OO[4], EE[4], EO[4];
        ld4p(fb + 1*BSUB, 2*q, OE);            // bOe
        ld4p(fb + 3*BSUB, 2*q, OO);            // bOo
        ld4p(fb + 0*BSUB, 2*q, EE);            // bEe
        ld4p(fb + 2*BSUB, 2*q, EO);            // bEo
        u64 O[8] = {OE[0],OO[0],OE[1],OO[1],OE[2],OO[2],OE[3],OO[3]};
        u64 E[8] = {EE[0],EO[0],EE[1],EO[1],EE[2],EO[2],EE[3],EO[3]};
        u64 cL[4], cH[4];
        qmf4p(O, E, bl, bh, cL, cH);
        float* o3 = out + OUT3_BASE + (size_t)b * (8 * 8192) + n0 + 4 * q;
        const int posLx = fam ? 3 : 0, posLy = fam ? 4 : 7;
        const int posHx = fam ? 2 : 1, posHy = fam ? 5 : 6;
        F2U l0{cL[0]}, l1{cL[1]}, l2{cL[2]}, l3{cL[3]};
        F2U h0{cH[0]}, h1{cH[1]}, h2{cH[2]}, h3{cH[3]};
        *(float4*)(o3 + posLx * 8192) = make_float4(l0.f.x, l1.f.x, l2.f.x, l3.f.x);
        *(float4*)(o3 + posLy * 8192) = make_float4(l0.f.y, l1.f.y, l2.f.y, l3.f.y);
        *(float4*)(o3 + posHx * 8192) = make_float4(h0.f.x, h1.f.x, h2.f.x, h3.f.x);
        *(float4*)(o3 + posHy * 8192) = make_float4(h0.f.y, h1.f.y, h2.f.y, h3.f.y);
    }
}

extern "C" void kernel_launch(void* const* d_in, const int* in_sizes, int n_in,
                              void* d_out, int out_size)
{
    const float* x    = (const float*)d_in[0];
    const float* kern = (const float*)d_in[1];
    float* out        = (float*)d_out;

    cudaFuncSetAttribute(mwpt_kernel,
                         cudaFuncAttributeMaxDynamicSharedMemorySize,
                         SMEM_BYTES);

    dim3 grid(8192 / N3, 128);   // 16 x 128 = 2048 blocks
    mwpt_kernel<<<grid, THREADS, SMEM_BYTES>>>(x, kern, out);
}